// round 1
// baseline (speedup 1.0000x reference)
#include <cuda_runtime.h>

#define B_   8
#define N_   784
#define DIM_ 384
#define H_   12
#define HD_  32
#define GS_  28
#define ROWS_ (B_*N_)   // 6272

#define TQ 64
#define TM 64
#define PSTR 72   // padded stride for P tiles (72 floats = 288B, 16B-aligned, conflict-free)

// Scratch (allocation-free rule: __device__ globals)
__device__ float g_q[B_*H_*N_*HD_];
__device__ float g_k[B_*H_*N_*HD_];
__device__ float g_v[B_*H_*N_*HD_];
__device__ float g_att[B_*N_*DIM_];
__device__ float g_pos[H_*N_*N_];   // 29.5 MB, normalized positional scores

// ---------------------------------------------------------------------------
// Kernel 1: precompute normalized positional softmax  pos[h][n][m]
// logit = w0*dx + w1*dy + w2*(dx^2+dy^2) + b_pos[h],
// dx = m%28 - n%28, dy = m/28 - n/28
// ---------------------------------------------------------------------------
__global__ void pos_kernel(const float* __restrict__ W_pos,
                           const float* __restrict__ b_pos) {
    int hn = blockIdx.x;               // 0 .. H_*N_-1
    int h = hn / N_, n = hn - h * N_;
    int nx = n % GS_, ny = n / GS_;
    float w0 = W_pos[h*3+0], w1 = W_pos[h*3+1], w2 = W_pos[h*3+2], bp = b_pos[h];
    int t = threadIdx.x;

    float lg[4];
    float lmax = -1e30f;
#pragma unroll
    for (int i = 0; i < 4; i++) {
        int m = t + i * 256;
        if (m < N_) {
            int mx = m % GS_, my = m / GS_;
            float dx = (float)(mx - nx), dy = (float)(my - ny);
            float v = fmaf(w2, dx*dx + dy*dy, fmaf(w1, dy, fmaf(w0, dx, bp)));
            lg[i] = v;
            lmax = fmaxf(lmax, v);
        } else lg[i] = -1e30f;
    }
    __shared__ float sred[8];
    __shared__ float ssum[8];
#pragma unroll
    for (int o = 16; o > 0; o >>= 1)
        lmax = fmaxf(lmax, __shfl_xor_sync(0xffffffffu, lmax, o));
    if ((t & 31) == 0) sred[t >> 5] = lmax;
    __syncthreads();
    float bmax = fmaxf(fmaxf(fmaxf(sred[0], sred[1]), fmaxf(sred[2], sred[3])),
                       fmaxf(fmaxf(sred[4], sred[5]), fmaxf(sred[6], sred[7])));

    float e[4]; float lsum = 0.f;
#pragma unroll
    for (int i = 0; i < 4; i++) { e[i] = __expf(lg[i] - bmax); lsum += e[i]; }
#pragma unroll
    for (int o = 16; o > 0; o >>= 1)
        lsum += __shfl_xor_sync(0xffffffffu, lsum, o);
    if ((t & 31) == 0) ssum[t >> 5] = lsum;
    __syncthreads();
    float tot = ((ssum[0]+ssum[1])+(ssum[2]+ssum[3]))+((ssum[4]+ssum[5])+(ssum[6]+ssum[7]));
    float inv = 1.f / tot;

    float* outp = g_pos + (size_t)hn * N_;
#pragma unroll
    for (int i = 0; i < 4; i++) {
        int m = t + i * 256;
        if (m < N_) outp[m] = e[i] * inv;
    }
}

// ---------------------------------------------------------------------------
// Kernel 2: GEMM  C[row][col] = sum_k X[row][k] * W[col][k]   (both k-major)
// sel 0/1/2 -> write g_q/g_k/g_v in [b][h][n][d] layout
// sel 3     -> X = g_att, write OUT[row][col] + bias[col]
// 64x64 tile, BK=16, 128 threads, 8x4 microtile
// ---------------------------------------------------------------------------
__global__ __launch_bounds__(128) void gemm_kernel(
    const float* __restrict__ Xin, const float* __restrict__ W,
    float* __restrict__ OUTp, const float* __restrict__ bias, int sel)
{
    __shared__ float Xt[16][64];
    __shared__ float Wt[16][64];

    const float* Xp = (sel == 3) ? (const float*)g_att : Xin;
    float* Op;
    if (sel == 0) Op = g_q; else if (sel == 1) Op = g_k;
    else if (sel == 2) Op = g_v; else Op = OUTp;

    int t = threadIdx.x;
    int row0 = blockIdx.y * 64;
    int col0 = blockIdx.x * 64;
    int ty = t >> 4, tx = t & 15;

    float acc[8][4];
#pragma unroll
    for (int i = 0; i < 8; i++)
#pragma unroll
        for (int j = 0; j < 4; j++) acc[i][j] = 0.f;

    for (int k0 = 0; k0 < DIM_; k0 += 16) {
#pragma unroll
        for (int l = 0; l < 2; l++) {
            int f4 = t + l * 128;            // 0..255
            int r  = f4 >> 2;
            int k4 = (f4 & 3) << 2;
            float4 vx = *(const float4*)&Xp[(size_t)(row0 + r) * DIM_ + k0 + k4];
            Xt[k4+0][r] = vx.x; Xt[k4+1][r] = vx.y; Xt[k4+2][r] = vx.z; Xt[k4+3][r] = vx.w;
            float4 vw = *(const float4*)&W[(size_t)(col0 + r) * DIM_ + k0 + k4];
            Wt[k4+0][r] = vw.x; Wt[k4+1][r] = vw.y; Wt[k4+2][r] = vw.z; Wt[k4+3][r] = vw.w;
        }
        __syncthreads();
#pragma unroll
        for (int k = 0; k < 16; k++) {
            float4 a0 = *(const float4*)&Xt[k][ty*8];
            float4 a1 = *(const float4*)&Xt[k][ty*8+4];
            float4 b4 = *(const float4*)&Wt[k][tx*4];
            float a[8] = {a0.x,a0.y,a0.z,a0.w,a1.x,a1.y,a1.z,a1.w};
            float bb[4] = {b4.x,b4.y,b4.z,b4.w};
#pragma unroll
            for (int i = 0; i < 8; i++)
#pragma unroll
                for (int j = 0; j < 4; j++)
                    acc[i][j] = fmaf(a[i], bb[j], acc[i][j]);
        }
        __syncthreads();
    }

    if (sel != 3) {
        int col = col0 + tx * 4;
        int h  = col >> 5;
        int dd = col & 31;
#pragma unroll
        for (int i = 0; i < 8; i++) {
            int row = row0 + ty * 8 + i;
            int b = row / N_, n = row - b * N_;
            float4 v4 = make_float4(acc[i][0], acc[i][1], acc[i][2], acc[i][3]);
            *(float4*)&Op[(((size_t)(b * H_ + h)) * N_ + n) * HD_ + dd] = v4;
        }
    } else {
        int col = col0 + tx * 4;
        float b0 = bias[col], b1 = bias[col+1], b2 = bias[col+2], b3 = bias[col+3];
#pragma unroll
        for (int i = 0; i < 8; i++) {
            int row = row0 + ty * 8 + i;
            float4 v4 = make_float4(acc[i][0]+b0, acc[i][1]+b1, acc[i][2]+b2, acc[i][3]+b3);
            *(float4*)&Op[(size_t)row * DIM_ + col] = v4;
        }
    }
}

// ---------------------------------------------------------------------------
// Kernel 3: fused gated attention per (b,h, 64-query tile).
// Single pass over m (no online softmax needed: |logit*scale| < ~2).
// Dual accumulators: O_patch (unnormalized exp * V) and O_pos (pos * V).
// out = (1-g)/rowsum * O_patch + g * O_pos
// ---------------------------------------------------------------------------
struct AttnSmem {
    float Qt[HD_][TQ];     // transposed: [k][r]
    float Kt[HD_][TM];     // transposed: [k][m]
    float Vs[TM][HD_];     // natural:    [m][d]
    float P1[TQ][PSTR];    // exp scores
    float P2[TQ][PSTR];    // pos scores
    float rowsum[TQ];
};

__global__ __launch_bounds__(128, 3) void attn_kernel(const float* __restrict__ gating) {
    extern __shared__ char s_raw[];
    AttnSmem& S = *reinterpret_cast<AttnSmem*>(s_raw);

    int t  = threadIdx.x;
    int bh = blockIdx.y;
    int b  = bh / H_, h = bh - b * H_;
    int q0 = blockIdx.x * TQ;

    const float* Qg   = g_q + (size_t)bh * N_ * HD_;
    const float* Kg   = g_k + (size_t)bh * N_ * HD_;
    const float* Vg   = g_v + (size_t)bh * N_ * HD_;
    const float* POSg = g_pos + (size_t)h * N_ * N_;

    float gate = 1.f / (1.f + __expf(-gating[h]));
    const float scale = 0.28867513459481287f;   // 12^-0.5

    int ty = t >> 4;     // S-phase: 8 rows
    int tx = t & 15;     // S-phase: 4 m
    int rg = t >> 3;     // PV-phase: 4 rows
    int dg = t & 7;      // PV-phase: 4 d

    // Load Q tile, transposed
#pragma unroll
    for (int l = 0; l < 4; l++) {
        int f4 = t + l * 128;              // 0..511
        int r  = f4 >> 3;
        int d4 = (f4 & 7) << 2;
        float4 v;
        if (q0 + r < N_) v = *(const float4*)&Qg[(size_t)(q0 + r) * HD_ + d4];
        else v = make_float4(0.f, 0.f, 0.f, 0.f);
        S.Qt[d4+0][r] = v.x; S.Qt[d4+1][r] = v.y; S.Qt[d4+2][r] = v.z; S.Qt[d4+3][r] = v.w;
    }

    float opatch[4][4];
    float opos[4][4];
    float rsum[8];
#pragma unroll
    for (int i = 0; i < 4; i++)
#pragma unroll
        for (int j = 0; j < 4; j++) { opatch[i][j] = 0.f; opos[i][j] = 0.f; }
#pragma unroll
    for (int i = 0; i < 8; i++) rsum[i] = 0.f;

    for (int m0 = 0; m0 < N_; m0 += TM) {
        __syncthreads();   // protect K/V/P smem from previous iteration
        // Load K (transposed) and V tiles
#pragma unroll
        for (int l = 0; l < 4; l++) {
            int f4 = t + l * 128;
            int m  = f4 >> 3;
            int d4 = (f4 & 7) << 2;
            float4 vk, vv;
            if (m0 + m < N_) {
                vk = *(const float4*)&Kg[(size_t)(m0 + m) * HD_ + d4];
                vv = *(const float4*)&Vg[(size_t)(m0 + m) * HD_ + d4];
            } else {
                vk = make_float4(0.f,0.f,0.f,0.f);
                vv = vk;
            }
            S.Kt[d4+0][m] = vk.x; S.Kt[d4+1][m] = vk.y; S.Kt[d4+2][m] = vk.z; S.Kt[d4+3][m] = vk.w;
            *(float4*)&S.Vs[m][d4] = vv;
        }
        __syncthreads();

        // S = Q K^T, 8r x 4m per thread
        float sacc[8][4];
#pragma unroll
        for (int i = 0; i < 8; i++)
#pragma unroll
            for (int j = 0; j < 4; j++) sacc[i][j] = 0.f;
#pragma unroll 8
        for (int k = 0; k < HD_; k++) {
            float4 a0 = *(const float4*)&S.Qt[k][ty*8];
            float4 a1 = *(const float4*)&S.Qt[k][ty*8+4];
            float4 b4 = *(const float4*)&S.Kt[k][tx*4];
            float a[8] = {a0.x,a0.y,a0.z,a0.w,a1.x,a1.y,a1.z,a1.w};
            float bb[4] = {b4.x,b4.y,b4.z,b4.w};
#pragma unroll
            for (int i = 0; i < 8; i++)
#pragma unroll
                for (int j = 0; j < 4; j++)
                    sacc[i][j] = fmaf(a[i], bb[j], sacc[i][j]);
        }

        // exp + mask + rowsum, stage P1 (exp) and P2 (pos) to smem
        int mb = m0 + tx * 4;
        bool mvalid = (mb < N_);            // N_ % 4 == 0 -> all-or-none
#pragma unroll
        for (int i = 0; i < 8; i++) {
            int r = ty * 8 + i;
            float e0 = mvalid ? __expf(sacc[i][0] * scale) : 0.f;
            float e1 = mvalid ? __expf(sacc[i][1] * scale) : 0.f;
            float e2 = mvalid ? __expf(sacc[i][2] * scale) : 0.f;
            float e3 = mvalid ? __expf(sacc[i][3] * scale) : 0.f;
            rsum[i] += (e0 + e1) + (e2 + e3);
            *(float4*)&S.P1[r][tx*4] = make_float4(e0, e1, e2, e3);
            float4 pv4;
            if (mvalid && (q0 + r) < N_)
                pv4 = *(const float4*)&POSg[(size_t)(q0 + r) * N_ + mb];
            else
                pv4 = make_float4(0.f, 0.f, 0.f, 0.f);
            *(float4*)&S.P2[r][tx*4] = pv4;
        }
        __syncthreads();

        // PV: 4r x 4d per thread, dual accumulation
#pragma unroll 4
        for (int mm = 0; mm < TM; mm += 4) {
            float p1a[4][4], p2a[4][4], va[4][4];
#pragma unroll
            for (int i = 0; i < 4; i++) {
                float4 u = *(const float4*)&S.P1[rg*4+i][mm];
                p1a[i][0]=u.x; p1a[i][1]=u.y; p1a[i][2]=u.z; p1a[i][3]=u.w;
                float4 w = *(const float4*)&S.P2[rg*4+i][mm];
                p2a[i][0]=w.x; p2a[i][1]=w.y; p2a[i][2]=w.z; p2a[i][3]=w.w;
            }
#pragma unroll
            for (int j = 0; j < 4; j++) {
                float4 u = *(const float4*)&S.Vs[mm+j][dg*4];
                va[j][0]=u.x; va[j][1]=u.y; va[j][2]=u.z; va[j][3]=u.w;
            }
#pragma unroll
            for (int i = 0; i < 4; i++)
#pragma unroll
                for (int j = 0; j < 4; j++)
#pragma unroll
                    for (int d = 0; d < 4; d++) {
                        opatch[i][d] = fmaf(p1a[i][j], va[j][d], opatch[i][d]);
                        opos[i][d]   = fmaf(p2a[i][j], va[j][d], opos[i][d]);
                    }
        }
    }

    // Reduce rowsum across the 16 tx-lanes sharing each ty group
#pragma unroll
    for (int i = 0; i < 8; i++) {
        float s = rsum[i];
        s += __shfl_xor_sync(0xffffffffu, s, 1);
        s += __shfl_xor_sync(0xffffffffu, s, 2);
        s += __shfl_xor_sync(0xffffffffu, s, 4);
        s += __shfl_xor_sync(0xffffffffu, s, 8);
        if (tx == 0) S.rowsum[ty*8 + i] = s;
    }
    __syncthreads();

    // Epilogue: out = (1-g)/rowsum * O_patch + g * O_pos   (attn sums to 1 -> no renorm)
    float omul = 1.f - gate;
#pragma unroll
    for (int i = 0; i < 4; i++) {
        int r = rg * 4 + i;
        int n = q0 + r;
        if (n < N_) {
            float inv = omul / S.rowsum[r];
            float4 o;
            o.x = opatch[i][0]*inv + gate*opos[i][0];
            o.y = opatch[i][1]*inv + gate*opos[i][1];
            o.z = opatch[i][2]*inv + gate*opos[i][2];
            o.w = opatch[i][3]*inv + gate*opos[i][3];
            *(float4*)&g_att[((size_t)b * N_ + n) * DIM_ + h * HD_ + dg * 4] = o;
        }
    }
}

// ---------------------------------------------------------------------------
extern "C" void kernel_launch(void* const* d_in, const int* in_sizes, int n_in,
                              void* d_out, int out_size) {
    const float* x      = (const float*)d_in[0];
    const float* Wq     = (const float*)d_in[1];
    const float* Wk     = (const float*)d_in[2];
    const float* Wv     = (const float*)d_in[3];
    const float* W_pos  = (const float*)d_in[4];
    const float* b_pos  = (const float*)d_in[5];
    const float* W_out  = (const float*)d_in[6];
    const float* b_out  = (const float*)d_in[7];
    const float* gating = (const float*)d_in[8];
    float* out = (float*)d_out;

    cudaFuncSetAttribute(attn_kernel, cudaFuncAttributeMaxDynamicSharedMemorySize,
                         (int)sizeof(AttnSmem));

    pos_kernel<<<H_ * N_, 256>>>(W_pos, b_pos);

    dim3 gg(DIM_ / 64, ROWS_ / 64);   // (6, 98)
    gemm_kernel<<<gg, 128>>>(x, Wq, nullptr, nullptr, 0);
    gemm_kernel<<<gg, 128>>>(x, Wk, nullptr, nullptr, 1);
    gemm_kernel<<<gg, 128>>>(x, Wv, nullptr, nullptr, 2);

    attn_kernel<<<dim3((N_ + TQ - 1) / TQ, B_ * H_), 128, sizeof(AttnSmem)>>>(gating);

    gemm_kernel<<<gg, 128>>>(nullptr, W_out, out, b_out, 3);
}

// round 3
// speedup vs baseline: 2.2852x; 2.2852x over previous
#include <cuda_runtime.h>
#include <cstdint>

#define B_   8
#define N_   784
#define DIM_ 384
#define H_   12
#define HD_  32
#define GS_  28
#define ROWS_ (B_*N_)   // 6272

// Scratch (allocation-free rule: __device__ globals)
__device__ float g_q[B_*H_*N_*HD_];
__device__ float g_k[B_*H_*N_*HD_];
__device__ float g_v[B_*H_*N_*HD_];
__device__ float g_att[B_*N_*DIM_];
__device__ float g_pos[H_*N_*N_];   // 29.5 MB normalized positional scores

// ---------------------------------------------------------------------------
// helpers: tf32 convert (round-to-nearest) + m16n8k8 tf32 mma
// ---------------------------------------------------------------------------
__device__ __forceinline__ unsigned f2tf(float f) {
    unsigned r; asm("cvt.rna.tf32.f32 %0, %1;" : "=r"(r) : "f"(f)); return r;
}
__device__ __forceinline__ void mma8(float4& d,
                                     unsigned a0, unsigned a1, unsigned a2, unsigned a3,
                                     unsigned b0, unsigned b1) {
    asm volatile("mma.sync.aligned.m16n8k8.row.col.f32.tf32.tf32.f32 "
                 "{%0,%1,%2,%3}, {%4,%5,%6,%7}, {%8,%9}, {%0,%1,%2,%3};\n"
                 : "+f"(d.x), "+f"(d.y), "+f"(d.z), "+f"(d.w)
                 : "r"(a0), "r"(a1), "r"(a2), "r"(a3), "r"(b0), "r"(b1));
}

// ---------------------------------------------------------------------------
// Kernel 1: normalized positional softmax  pos[h][n][m]
// ---------------------------------------------------------------------------
__global__ void pos_kernel(const float* __restrict__ W_pos,
                           const float* __restrict__ b_pos) {
    int hn = blockIdx.x;
    int h = hn / N_, n = hn - h * N_;
    int nx = n % GS_, ny = n / GS_;
    float w0 = W_pos[h*3+0], w1 = W_pos[h*3+1], w2 = W_pos[h*3+2], bp = b_pos[h];
    int t = threadIdx.x;

    float lg[4];
    float lmax = -1e30f;
#pragma unroll
    for (int i = 0; i < 4; i++) {
        int m = t + i * 256;
        if (m < N_) {
            int mx = m % GS_, my = m / GS_;
            float dx = (float)(mx - nx), dy = (float)(my - ny);
            float v = fmaf(w2, dx*dx + dy*dy, fmaf(w1, dy, fmaf(w0, dx, bp)));
            lg[i] = v;
            lmax = fmaxf(lmax, v);
        } else lg[i] = -1e30f;
    }
    __shared__ float sred[8];
    __shared__ float ssum[8];
#pragma unroll
    for (int o = 16; o > 0; o >>= 1)
        lmax = fmaxf(lmax, __shfl_xor_sync(0xffffffffu, lmax, o));
    if ((t & 31) == 0) sred[t >> 5] = lmax;
    __syncthreads();
    float bmax = fmaxf(fmaxf(fmaxf(sred[0], sred[1]), fmaxf(sred[2], sred[3])),
                       fmaxf(fmaxf(sred[4], sred[5]), fmaxf(sred[6], sred[7])));

    float e[4]; float lsum = 0.f;
#pragma unroll
    for (int i = 0; i < 4; i++) { e[i] = __expf(lg[i] - bmax); lsum += e[i]; }
#pragma unroll
    for (int o = 16; o > 0; o >>= 1)
        lsum += __shfl_xor_sync(0xffffffffu, lsum, o);
    if ((t & 31) == 0) ssum[t >> 5] = lsum;
    __syncthreads();
    float tot = ((ssum[0]+ssum[1])+(ssum[2]+ssum[3]))+((ssum[4]+ssum[5])+(ssum[6]+ssum[7]));
    float inv = 1.f / tot;

    float* outp = g_pos + (size_t)hn * N_;
#pragma unroll
    for (int i = 0; i < 4; i++) {
        int m = t + i * 256;
        if (m < N_) outp[m] = e[i] * inv;
    }
}

// ---------------------------------------------------------------------------
// Kernel 2: tf32 tensor-core GEMM  C[row][col] = sum_k X[row][k]*W[col][k]
// 64x64 tile, BK=32, 128 threads (4 warps, 2x2), each warp 32x32 via m16n8k8
// ---------------------------------------------------------------------------
#define GSTR 36
__global__ __launch_bounds__(128) void gemm_kernel(
    const float* __restrict__ Xin, const float* __restrict__ W,
    float* __restrict__ OUTp, const float* __restrict__ bias, int sel)
{
    __shared__ unsigned Xs[64][GSTR];
    __shared__ unsigned Ws[64][GSTR];

    const float* Xp = (sel == 3) ? (const float*)g_att : Xin;
    float* Op;
    if (sel == 0) Op = g_q; else if (sel == 1) Op = g_k;
    else if (sel == 2) Op = g_v; else Op = OUTp;

    int t = threadIdx.x;
    int w = t >> 5, lane = t & 31;
    int ly = lane >> 2, lx = lane & 3;
    int wr = w >> 1, wc = w & 1;
    int row0 = blockIdx.y * 64, col0 = blockIdx.x * 64;

    float4 acc[2][4];
#pragma unroll
    for (int i = 0; i < 2; i++)
#pragma unroll
        for (int j = 0; j < 4; j++) acc[i][j] = make_float4(0.f, 0.f, 0.f, 0.f);

    for (int k0 = 0; k0 < DIM_; k0 += 32) {
        __syncthreads();
#pragma unroll
        for (int l = 0; l < 4; l++) {
            int idx = t + l * 128;
            int r = idx >> 3, kq = (idx & 7) << 2;
            float4 vx = *(const float4*)&Xp[(size_t)(row0 + r) * DIM_ + k0 + kq];
            uint4 ux; ux.x = f2tf(vx.x); ux.y = f2tf(vx.y); ux.z = f2tf(vx.z); ux.w = f2tf(vx.w);
            *(uint4*)&Xs[r][kq] = ux;
            float4 vw = *(const float4*)&W[(size_t)(col0 + r) * DIM_ + k0 + kq];
            uint4 uw; uw.x = f2tf(vw.x); uw.y = f2tf(vw.y); uw.z = f2tf(vw.z); uw.w = f2tf(vw.w);
            *(uint4*)&Ws[r][kq] = uw;
        }
        __syncthreads();
#pragma unroll
        for (int kk = 0; kk < 4; kk++) {
            int K0 = kk * 8;
            unsigned a[2][4];
#pragma unroll
            for (int mi = 0; mi < 2; mi++) {
                int rb = wr * 32 + mi * 16 + ly;
                a[mi][0] = Xs[rb][K0 + lx];
                a[mi][1] = Xs[rb + 8][K0 + lx];
                a[mi][2] = Xs[rb][K0 + lx + 4];
                a[mi][3] = Xs[rb + 8][K0 + lx + 4];
            }
#pragma unroll
            for (int nt = 0; nt < 4; nt++) {
                int cb = wc * 32 + nt * 8 + ly;
                unsigned b0 = Ws[cb][K0 + lx];
                unsigned b1 = Ws[cb][K0 + lx + 4];
                mma8(acc[0][nt], a[0][0], a[0][1], a[0][2], a[0][3], b0, b1);
                mma8(acc[1][nt], a[1][0], a[1][1], a[1][2], a[1][3], b0, b1);
            }
        }
    }

    if (sel != 3) {
        int h = (col0 + wc * 32) >> 5;       // one head per warp-col block
#pragma unroll
        for (int mi = 0; mi < 2; mi++) {
            int row = row0 + wr * 32 + mi * 16 + ly;
#pragma unroll
            for (int nt = 0; nt < 4; nt++) {
                int d = nt * 8 + lx * 2;
                {
                    int b = row / N_, n = row - b * N_;
                    float2 v; v.x = acc[mi][nt].x; v.y = acc[mi][nt].y;
                    *(float2*)&Op[(((size_t)(b * H_ + h)) * N_ + n) * HD_ + d] = v;
                }
                {
                    int row2 = row + 8;
                    int b = row2 / N_, n = row2 - b * N_;
                    float2 v; v.x = acc[mi][nt].z; v.y = acc[mi][nt].w;
                    *(float2*)&Op[(((size_t)(b * H_ + h)) * N_ + n) * HD_ + d] = v;
                }
            }
        }
    } else {
#pragma unroll
        for (int mi = 0; mi < 2; mi++) {
            int row = row0 + wr * 32 + mi * 16 + ly;
#pragma unroll
            for (int nt = 0; nt < 4; nt++) {
                int col = col0 + wc * 32 + nt * 8 + lx * 2;
                float b0 = bias[col], b1 = bias[col + 1];
                float2 v0; v0.x = acc[mi][nt].x + b0; v0.y = acc[mi][nt].y + b1;
                *(float2*)&Op[(size_t)row * DIM_ + col] = v0;
                float2 v1; v1.x = acc[mi][nt].z + b0; v1.y = acc[mi][nt].w + b1;
                *(float2*)&Op[(size_t)(row + 8) * DIM_ + col] = v1;
            }
        }
    }
}

// ---------------------------------------------------------------------------
// Kernel 3: fused gated attention with tf32 mma.
// ---------------------------------------------------------------------------
#define QSTR 36
#define VSTR 40
#define PSTR 68
struct ASmem {
    unsigned Qs[64][QSTR];
    unsigned Ks[64][QSTR];
    unsigned Vs[64][VSTR];
    unsigned P1[64][PSTR];
    unsigned P2[64][PSTR];
};

__global__ __launch_bounds__(128) void attn_kernel(const float* __restrict__ gating) {
    extern __shared__ char sraw[];
    ASmem& S = *reinterpret_cast<ASmem*>(sraw);

    int t = threadIdx.x, w = t >> 5, lane = t & 31;
    int ly = lane >> 2, lx = lane & 3;
    int bh = blockIdx.y;
    int b = bh / H_, h = bh - b * H_;
    int q0 = blockIdx.x * 64;
    int R0 = w * 16;

    const float* Qg   = g_q + (size_t)bh * N_ * HD_;
    const float* Kg   = g_k + (size_t)bh * N_ * HD_;
    const float* Vg   = g_v + (size_t)bh * N_ * HD_;
    const float* POSg = g_pos + (size_t)h * N_ * N_;

    float gate = 1.f / (1.f + __expf(-gating[h]));
    const float scale = 0.28867513459481287f;   // 12^-0.5, folded into Q

    // Q tile fill (scaled, tf32): 64 rows x 32 floats = 512 float4
#pragma unroll
    for (int l = 0; l < 4; l++) {
        int idx = t + l * 128;
        int r = idx >> 3, dq = (idx & 7) << 2;
        float4 v = make_float4(0.f, 0.f, 0.f, 0.f);
        if (q0 + r < N_) v = *(const float4*)&Qg[(size_t)(q0 + r) * HD_ + dq];
        uint4 u; u.x = f2tf(v.x * scale); u.y = f2tf(v.y * scale);
        u.z = f2tf(v.z * scale); u.w = f2tf(v.w * scale);
        *(uint4*)&S.Qs[r][dq] = u;
    }

    float4 opat[4], opos[4];
#pragma unroll
    for (int i = 0; i < 4; i++) { opat[i] = make_float4(0.f,0.f,0.f,0.f); opos[i] = opat[i]; }
    float rs0 = 0.f, rs1 = 0.f;

    for (int it = 0; it < 13; it++) {
        int m0 = it * 64;
        __syncthreads();                 // protect K/V/P2 (and first-iter Q) readers
        // K, V tiles: 64 rows x 32 floats each = 512 float4 each
#pragma unroll
        for (int l = 0; l < 4; l++) {
            int idx = t + l * 128;
            int r = idx >> 3, dq = (idx & 7) << 2;
            float4 vk = make_float4(0.f,0.f,0.f,0.f), vv = vk;
            if (m0 + r < N_) {
                vk = *(const float4*)&Kg[(size_t)(m0 + r) * HD_ + dq];
                vv = *(const float4*)&Vg[(size_t)(m0 + r) * HD_ + dq];
            }
            uint4 uk; uk.x = f2tf(vk.x); uk.y = f2tf(vk.y); uk.z = f2tf(vk.z); uk.w = f2tf(vk.w);
            *(uint4*)&S.Ks[r][dq] = uk;
            uint4 uv; uv.x = f2tf(vv.x); uv.y = f2tf(vv.y); uv.z = f2tf(vv.z); uv.w = f2tf(vv.w);
            *(uint4*)&S.Vs[r][dq] = uv;
        }
        // P2 (pos) tile: 64 rows x 64 cols = 1024 float4
#pragma unroll
        for (int l = 0; l < 8; l++) {
            int idx = t + l * 128;
            int r = idx >> 4, cq = (idx & 15) << 2;
            float4 p = make_float4(0.f,0.f,0.f,0.f);
            if (q0 + r < N_ && m0 + cq < N_)
                p = *(const float4*)&POSg[(size_t)(q0 + r) * N_ + m0 + cq];
            uint4 up; up.x = f2tf(p.x); up.y = f2tf(p.y); up.z = f2tf(p.z); up.w = f2tf(p.w);
            *(uint4*)&S.P2[r][cq] = up;
        }
        __syncthreads();

        // S = Q K^T  (16 x 64 per warp)
        float4 sacc[8];
#pragma unroll
        for (int i = 0; i < 8; i++) sacc[i] = make_float4(0.f,0.f,0.f,0.f);
#pragma unroll
        for (int kk = 0; kk < 4; kk++) {
            int K0 = kk * 8;
            unsigned a0 = S.Qs[R0 + ly][K0 + lx];
            unsigned a1 = S.Qs[R0 + ly + 8][K0 + lx];
            unsigned a2 = S.Qs[R0 + ly][K0 + lx + 4];
            unsigned a3 = S.Qs[R0 + ly + 8][K0 + lx + 4];
#pragma unroll
            for (int nt = 0; nt < 8; nt++) {
                unsigned b0 = S.Ks[nt * 8 + ly][K0 + lx];
                unsigned b1 = S.Ks[nt * 8 + ly][K0 + lx + 4];
                mma8(sacc[nt], a0, a1, a2, a3, b0, b1);
            }
        }

        // exp + rowsum + stage P1 (warp-private rows)
#pragma unroll
        for (int nt = 0; nt < 8; nt++) {
            int mc = m0 + nt * 8 + lx * 2;
            bool mv = (mc < N_);
            float ex = mv ? __expf(sacc[nt].x) : 0.f;
            float ey = mv ? __expf(sacc[nt].y) : 0.f;
            float ez = mv ? __expf(sacc[nt].z) : 0.f;
            float ew = mv ? __expf(sacc[nt].w) : 0.f;
            rs0 += ex + ey;
            rs1 += ez + ew;
            uint2 u01; u01.x = f2tf(ex); u01.y = f2tf(ey);
            uint2 u23; u23.x = f2tf(ez); u23.y = f2tf(ew);
            *(uint2*)&S.P1[R0 + ly][nt * 8 + lx * 2] = u01;
            *(uint2*)&S.P1[R0 + ly + 8][nt * 8 + lx * 2] = u23;
        }
        __syncwarp();

        // PV: dual accumulate (16 x 32 per warp)
#pragma unroll
        for (int kk = 0; kk < 8; kk++) {
            int K0 = kk * 8;
            unsigned p0 = S.P1[R0 + ly][K0 + lx];
            unsigned p1 = S.P1[R0 + ly + 8][K0 + lx];
            unsigned p2 = S.P1[R0 + ly][K0 + lx + 4];
            unsigned p3 = S.P1[R0 + ly + 8][K0 + lx + 4];
            unsigned c0 = S.P2[R0 + ly][K0 + lx];
            unsigned c1 = S.P2[R0 + ly + 8][K0 + lx];
            unsigned c2 = S.P2[R0 + ly][K0 + lx + 4];
            unsigned c3 = S.P2[R0 + ly + 8][K0 + lx + 4];
#pragma unroll
            for (int nt = 0; nt < 4; nt++) {
                unsigned b0 = S.Vs[K0 + lx][nt * 8 + ly];
                unsigned b1 = S.Vs[K0 + lx + 4][nt * 8 + ly];
                mma8(opat[nt], p0, p1, p2, p3, b0, b1);
                mma8(opos[nt], c0, c1, c2, c3, b0, b1);
            }
        }
    }

    // rowsum reduce over the quad (lanes sharing a row)
    rs0 += __shfl_xor_sync(0xffffffffu, rs0, 1);
    rs0 += __shfl_xor_sync(0xffffffffu, rs0, 2);
    rs1 += __shfl_xor_sync(0xffffffffu, rs1, 1);
    rs1 += __shfl_xor_sync(0xffffffffu, rs1, 2);
    float inv0 = (1.f - gate) / rs0;
    float inv1 = (1.f - gate) / rs1;

    // epilogue: out = (1-g)/rowsum * O_patch + g * O_pos (attn sums to 1)
    int n0r = q0 + R0 + ly;
    int n1r = n0r + 8;
#pragma unroll
    for (int nt = 0; nt < 4; nt++) {
        int d = nt * 8 + lx * 2;
        if (n0r < N_) {
            float2 o;
            o.x = opat[nt].x * inv0 + gate * opos[nt].x;
            o.y = opat[nt].y * inv0 + gate * opos[nt].y;
            *(float2*)&g_att[((size_t)b * N_ + n0r) * DIM_ + h * HD_ + d] = o;
        }
        if (n1r < N_) {
            float2 o;
            o.x = opat[nt].z * inv1 + gate * opos[nt].z;
            o.y = opat[nt].w * inv1 + gate * opos[nt].w;
            *(float2*)&g_att[((size_t)b * N_ + n1r) * DIM_ + h * HD_ + d] = o;
        }
    }
}

// ---------------------------------------------------------------------------
extern "C" void kernel_launch(void* const* d_in, const int* in_sizes, int n_in,
                              void* d_out, int out_size) {
    const float* x      = (const float*)d_in[0];
    const float* Wq     = (const float*)d_in[1];
    const float* Wk     = (const float*)d_in[2];
    const float* Wv     = (const float*)d_in[3];
    const float* W_pos  = (const float*)d_in[4];
    const float* b_pos  = (const float*)d_in[5];
    const float* W_out  = (const float*)d_in[6];
    const float* b_out  = (const float*)d_in[7];
    const float* gating = (const float*)d_in[8];
    float* out = (float*)d_out;

    cudaFuncSetAttribute(attn_kernel, cudaFuncAttributeMaxDynamicSharedMemorySize,
                         (int)sizeof(ASmem));

    pos_kernel<<<H_ * N_, 256>>>(W_pos, b_pos);

    dim3 gg(DIM_ / 64, ROWS_ / 64);   // (6, 98)
    gemm_kernel<<<gg, 128>>>(x, Wq, nullptr, nullptr, 0);
    gemm_kernel<<<gg, 128>>>(x, Wk, nullptr, nullptr, 1);
    gemm_kernel<<<gg, 128>>>(x, Wv, nullptr, nullptr, 2);

    attn_kernel<<<dim3(13, B_ * H_), 128, sizeof(ASmem)>>>(gating);

    gemm_kernel<<<gg, 128>>>(nullptr, W_out, out, b_out, 3);
}

// round 4
// speedup vs baseline: 2.7042x; 1.1834x over previous
#include <cuda_runtime.h>
#include <cstdint>

#define B_   8
#define N_   784
#define DIM_ 384
#define H_   12
#define HD_  32
#define GS_  28
#define ROWS_ (B_*N_)   // 6272
#define SCALE_ 0.28867513459481287f   // 12^-0.5

// Scratch (allocation-free rule: __device__ globals)
// g_q/g_k/g_v/g_pos hold tf32 bit patterns (producers pre-convert).
__device__ float g_q[B_*H_*N_*HD_];
__device__ float g_k[B_*H_*N_*HD_];
__device__ float g_v[B_*H_*N_*HD_];
__device__ float g_att[B_*N_*DIM_];
__device__ float g_pos[H_*N_*N_];   // 29.5 MB normalized positional scores (tf32 bits)

// ---------------------------------------------------------------------------
// helpers
// ---------------------------------------------------------------------------
__device__ __forceinline__ unsigned f2tf(float f) {
    unsigned r; asm("cvt.rna.tf32.f32 %0, %1;" : "=r"(r) : "f"(f)); return r;
}
__device__ __forceinline__ void mma8(float4& d,
                                     unsigned a0, unsigned a1, unsigned a2, unsigned a3,
                                     unsigned b0, unsigned b1) {
    asm volatile("mma.sync.aligned.m16n8k8.row.col.f32.tf32.tf32.f32 "
                 "{%0,%1,%2,%3}, {%4,%5,%6,%7}, {%8,%9}, {%0,%1,%2,%3};\n"
                 : "+f"(d.x), "+f"(d.y), "+f"(d.z), "+f"(d.w)
                 : "r"(a0), "r"(a1), "r"(a2), "r"(a3), "r"(b0), "r"(b1));
}
__device__ __forceinline__ void cpa16(void* s, const void* g, bool pred) {
    unsigned sa = (unsigned)__cvta_generic_to_shared(s);
    int sz = pred ? 16 : 0;
    asm volatile("cp.async.cg.shared.global [%0], [%1], 16, %2;\n"
                 :: "r"(sa), "l"(g), "r"(sz) : "memory");
}
__device__ __forceinline__ void cpa_commit() {
    asm volatile("cp.async.commit_group;\n" ::: "memory");
}

// ---------------------------------------------------------------------------
// Kernel 1: normalized positional softmax  pos[h][n][m]  (writes tf32 bits)
// ---------------------------------------------------------------------------
__global__ void pos_kernel(const float* __restrict__ W_pos,
                           const float* __restrict__ b_pos) {
    int hn = blockIdx.x;
    int h = hn / N_, n = hn - h * N_;
    int nx = n % GS_, ny = n / GS_;
    float w0 = W_pos[h*3+0], w1 = W_pos[h*3+1], w2 = W_pos[h*3+2], bp = b_pos[h];
    int t = threadIdx.x;

    float lg[4];
    float lmax = -1e30f;
#pragma unroll
    for (int i = 0; i < 4; i++) {
        int m = t + i * 256;
        if (m < N_) {
            int mx = m % GS_, my = m / GS_;
            float dx = (float)(mx - nx), dy = (float)(my - ny);
            float v = fmaf(w2, dx*dx + dy*dy, fmaf(w1, dy, fmaf(w0, dx, bp)));
            lg[i] = v;
            lmax = fmaxf(lmax, v);
        } else lg[i] = -1e30f;
    }
    __shared__ float sred[8];
    __shared__ float ssum[8];
#pragma unroll
    for (int o = 16; o > 0; o >>= 1)
        lmax = fmaxf(lmax, __shfl_xor_sync(0xffffffffu, lmax, o));
    if ((t & 31) == 0) sred[t >> 5] = lmax;
    __syncthreads();
    float bmax = fmaxf(fmaxf(fmaxf(sred[0], sred[1]), fmaxf(sred[2], sred[3])),
                       fmaxf(fmaxf(sred[4], sred[5]), fmaxf(sred[6], sred[7])));

    float e[4]; float lsum = 0.f;
#pragma unroll
    for (int i = 0; i < 4; i++) { e[i] = __expf(lg[i] - bmax); lsum += e[i]; }
#pragma unroll
    for (int o = 16; o > 0; o >>= 1)
        lsum += __shfl_xor_sync(0xffffffffu, lsum, o);
    if ((t & 31) == 0) ssum[t >> 5] = lsum;
    __syncthreads();
    float tot = ((ssum[0]+ssum[1])+(ssum[2]+ssum[3]))+((ssum[4]+ssum[5])+(ssum[6]+ssum[7]));
    float inv = 1.f / tot;

    float* outp = g_pos + (size_t)hn * N_;
#pragma unroll
    for (int i = 0; i < 4; i++) {
        int m = t + i * 256;
        if (m < N_) outp[m] = __uint_as_float(f2tf(e[i] * inv));
    }
}

// ---------------------------------------------------------------------------
// Kernel 2: fused QKV tf32 GEMM, software-pipelined (2-stage smem).
// Column space 1152 = [Wq | Wk | Wv]. Writes tf32 bits (Q pre-scaled).
// ---------------------------------------------------------------------------
#define GSTR 36
__global__ __launch_bounds__(128) void gemm_qkv(
    const float* __restrict__ X, const float* __restrict__ Wq,
    const float* __restrict__ Wk, const float* __restrict__ Wv)
{
    __shared__ unsigned Xs[2][64][GSTR];
    __shared__ unsigned Ws[2][64][GSTR];

    int t = threadIdx.x, w = t >> 5, lane = t & 31;
    int ly = lane >> 2, lx = lane & 3;
    int wr = w >> 1, wc = w & 1;
    int row0 = blockIdx.y * 64, col0 = blockIdx.x * 64;
    int wsel = col0 / DIM_;
    int colw = col0 - wsel * DIM_;
    const float* W = (wsel == 0) ? Wq : (wsel == 1) ? Wk : Wv;
    float* Op = (wsel == 0) ? g_q : (wsel == 1) ? g_k : g_v;
    float scale = (wsel == 0) ? SCALE_ : 1.f;

    float4 rx[4], rw[4];
#pragma unroll
    for (int l = 0; l < 4; l++) {
        int idx = t + l * 128;
        int r = idx >> 3, kq = (idx & 7) << 2;
        rx[l] = *(const float4*)&X[(size_t)(row0 + r) * DIM_ + kq];
        rw[l] = *(const float4*)&W[(size_t)(colw + r) * DIM_ + kq];
    }
#pragma unroll
    for (int l = 0; l < 4; l++) {
        int idx = t + l * 128;
        int r = idx >> 3, kq = (idx & 7) << 2;
        *(uint4*)&Xs[0][r][kq] = make_uint4(f2tf(rx[l].x), f2tf(rx[l].y), f2tf(rx[l].z), f2tf(rx[l].w));
        *(uint4*)&Ws[0][r][kq] = make_uint4(f2tf(rw[l].x), f2tf(rw[l].y), f2tf(rw[l].z), f2tf(rw[l].w));
    }
    __syncthreads();

    float4 acc[2][4];
#pragma unroll
    for (int i = 0; i < 2; i++)
#pragma unroll
        for (int j = 0; j < 4; j++) acc[i][j] = make_float4(0.f, 0.f, 0.f, 0.f);

    for (int ki = 0; ki < 12; ki++) {
        int cur = ki & 1;
        if (ki < 11) {
            int k0 = (ki + 1) * 32;
#pragma unroll
            for (int l = 0; l < 4; l++) {
                int idx = t + l * 128;
                int r = idx >> 3, kq = (idx & 7) << 2;
                rx[l] = *(const float4*)&X[(size_t)(row0 + r) * DIM_ + k0 + kq];
                rw[l] = *(const float4*)&W[(size_t)(colw + r) * DIM_ + k0 + kq];
            }
        }
#pragma unroll
        for (int kk = 0; kk < 4; kk++) {
            int K0 = kk * 8;
            unsigned a[2][4];
#pragma unroll
            for (int mi = 0; mi < 2; mi++) {
                int rb = wr * 32 + mi * 16 + ly;
                a[mi][0] = Xs[cur][rb][K0 + lx];
                a[mi][1] = Xs[cur][rb + 8][K0 + lx];
                a[mi][2] = Xs[cur][rb][K0 + lx + 4];
                a[mi][3] = Xs[cur][rb + 8][K0 + lx + 4];
            }
#pragma unroll
            for (int nt = 0; nt < 4; nt++) {
                int cb = wc * 32 + nt * 8 + ly;
                unsigned b0 = Ws[cur][cb][K0 + lx];
                unsigned b1 = Ws[cur][cb][K0 + lx + 4];
                mma8(acc[0][nt], a[0][0], a[0][1], a[0][2], a[0][3], b0, b1);
                mma8(acc[1][nt], a[1][0], a[1][1], a[1][2], a[1][3], b0, b1);
            }
        }
        if (ki < 11) {
            int nxt = (ki + 1) & 1;
#pragma unroll
            for (int l = 0; l < 4; l++) {
                int idx = t + l * 128;
                int r = idx >> 3, kq = (idx & 7) << 2;
                *(uint4*)&Xs[nxt][r][kq] = make_uint4(f2tf(rx[l].x), f2tf(rx[l].y), f2tf(rx[l].z), f2tf(rx[l].w));
                *(uint4*)&Ws[nxt][r][kq] = make_uint4(f2tf(rw[l].x), f2tf(rw[l].y), f2tf(rw[l].z), f2tf(rw[l].w));
            }
        }
        __syncthreads();
    }

    // epilogue: write tf32 bits, [b][h][n][d] layout, Q pre-scaled
    int h = (colw + wc * 32) >> 5;
#pragma unroll
    for (int mi = 0; mi < 2; mi++) {
        int row = row0 + wr * 32 + mi * 16 + ly;
#pragma unroll
        for (int nt = 0; nt < 4; nt++) {
            int d = nt * 8 + lx * 2;
            {
                int b = row / N_, n = row - b * N_;
                float2 v;
                v.x = __uint_as_float(f2tf(acc[mi][nt].x * scale));
                v.y = __uint_as_float(f2tf(acc[mi][nt].y * scale));
                *(float2*)&Op[(((size_t)(b * H_ + h)) * N_ + n) * HD_ + d] = v;
            }
            {
                int row2 = row + 8;
                int b = row2 / N_, n = row2 - b * N_;
                float2 v;
                v.x = __uint_as_float(f2tf(acc[mi][nt].z * scale));
                v.y = __uint_as_float(f2tf(acc[mi][nt].w * scale));
                *(float2*)&Op[(((size_t)(b * H_ + h)) * N_ + n) * HD_ + d] = v;
            }
        }
    }
}

// ---------------------------------------------------------------------------
// Kernel 2b: out-projection tf32 GEMM (same pipeline), + bias, plain fp32 out
// ---------------------------------------------------------------------------
__global__ __launch_bounds__(128) void gemm_out(
    const float* __restrict__ W, const float* __restrict__ bias,
    float* __restrict__ OUTp)
{
    __shared__ unsigned Xs[2][64][GSTR];
    __shared__ unsigned Ws[2][64][GSTR];

    int t = threadIdx.x, w = t >> 5, lane = t & 31;
    int ly = lane >> 2, lx = lane & 3;
    int wr = w >> 1, wc = w & 1;
    int row0 = blockIdx.y * 64, col0 = blockIdx.x * 64;
    const float* X = g_att;

    float4 rx[4], rw[4];
#pragma unroll
    for (int l = 0; l < 4; l++) {
        int idx = t + l * 128;
        int r = idx >> 3, kq = (idx & 7) << 2;
        rx[l] = *(const float4*)&X[(size_t)(row0 + r) * DIM_ + kq];
        rw[l] = *(const float4*)&W[(size_t)(col0 + r) * DIM_ + kq];
    }
#pragma unroll
    for (int l = 0; l < 4; l++) {
        int idx = t + l * 128;
        int r = idx >> 3, kq = (idx & 7) << 2;
        *(uint4*)&Xs[0][r][kq] = make_uint4(f2tf(rx[l].x), f2tf(rx[l].y), f2tf(rx[l].z), f2tf(rx[l].w));
        *(uint4*)&Ws[0][r][kq] = make_uint4(f2tf(rw[l].x), f2tf(rw[l].y), f2tf(rw[l].z), f2tf(rw[l].w));
    }
    __syncthreads();

    float4 acc[2][4];
#pragma unroll
    for (int i = 0; i < 2; i++)
#pragma unroll
        for (int j = 0; j < 4; j++) acc[i][j] = make_float4(0.f, 0.f, 0.f, 0.f);

    for (int ki = 0; ki < 12; ki++) {
        int cur = ki & 1;
        if (ki < 11) {
            int k0 = (ki + 1) * 32;
#pragma unroll
            for (int l = 0; l < 4; l++) {
                int idx = t + l * 128;
                int r = idx >> 3, kq = (idx & 7) << 2;
                rx[l] = *(const float4*)&X[(size_t)(row0 + r) * DIM_ + k0 + kq];
                rw[l] = *(const float4*)&W[(size_t)(col0 + r) * DIM_ + k0 + kq];
            }
        }
#pragma unroll
        for (int kk = 0; kk < 4; kk++) {
            int K0 = kk * 8;
            unsigned a[2][4];
#pragma unroll
            for (int mi = 0; mi < 2; mi++) {
                int rb = wr * 32 + mi * 16 + ly;
                a[mi][0] = Xs[cur][rb][K0 + lx];
                a[mi][1] = Xs[cur][rb + 8][K0 + lx];
                a[mi][2] = Xs[cur][rb][K0 + lx + 4];
                a[mi][3] = Xs[cur][rb + 8][K0 + lx + 4];
            }
#pragma unroll
            for (int nt = 0; nt < 4; nt++) {
                int cb = wc * 32 + nt * 8 + ly;
                unsigned b0 = Ws[cur][cb][K0 + lx];
                unsigned b1 = Ws[cur][cb][K0 + lx + 4];
                mma8(acc[0][nt], a[0][0], a[0][1], a[0][2], a[0][3], b0, b1);
                mma8(acc[1][nt], a[1][0], a[1][1], a[1][2], a[1][3], b0, b1);
            }
        }
        if (ki < 11) {
            int nxt = (ki + 1) & 1;
#pragma unroll
            for (int l = 0; l < 4; l++) {
                int idx = t + l * 128;
                int r = idx >> 3, kq = (idx & 7) << 2;
                *(uint4*)&Xs[nxt][r][kq] = make_uint4(f2tf(rx[l].x), f2tf(rx[l].y), f2tf(rx[l].z), f2tf(rx[l].w));
                *(uint4*)&Ws[nxt][r][kq] = make_uint4(f2tf(rw[l].x), f2tf(rw[l].y), f2tf(rw[l].z), f2tf(rw[l].w));
            }
        }
        __syncthreads();
    }

#pragma unroll
    for (int mi = 0; mi < 2; mi++) {
        int row = row0 + wr * 32 + mi * 16 + ly;
#pragma unroll
        for (int nt = 0; nt < 4; nt++) {
            int col = col0 + wc * 32 + nt * 8 + lx * 2;
            float b0 = bias[col], b1 = bias[col + 1];
            float2 v0; v0.x = acc[mi][nt].x + b0; v0.y = acc[mi][nt].y + b1;
            *(float2*)&OUTp[(size_t)row * DIM_ + col] = v0;
            float2 v1; v1.x = acc[mi][nt].z + b0; v1.y = acc[mi][nt].w + b1;
            *(float2*)&OUTp[(size_t)(row + 8) * DIM_ + col] = v1;
        }
    }
}

// ---------------------------------------------------------------------------
// Kernel 3: fused gated attention, cp.async double-buffered mainloop.
// Inputs g_q (pre-scaled tf32 bits), g_k, g_v, g_pos (tf32 bits).
// ---------------------------------------------------------------------------
#define QSTR 36
#define VSTR 40
#define PSTR 68
struct ASmem {
    unsigned Qs[64][QSTR];
    unsigned P1[64][PSTR];
    unsigned Ks[2][64][QSTR];
    unsigned Vs[2][64][VSTR];
    unsigned P2[2][64][PSTR];
};

__global__ __launch_bounds__(128) void attn_kernel(const float* __restrict__ gating) {
    extern __shared__ char sraw[];
    ASmem& S = *reinterpret_cast<ASmem*>(sraw);

    int t = threadIdx.x, w = t >> 5, lane = t & 31;
    int ly = lane >> 2, lx = lane & 3;
    int bh = blockIdx.y;
    int b = bh / H_, h = bh - b * H_;
    int q0 = blockIdx.x * 64;
    int R0 = w * 16;

    const float* Qg   = g_q + (size_t)bh * N_ * HD_;
    const float* Kg   = g_k + (size_t)bh * N_ * HD_;
    const float* Vg   = g_v + (size_t)bh * N_ * HD_;
    const float* POSg = g_pos + (size_t)h * N_ * N_;

    float gate = 1.f / (1.f + __expf(-gating[h]));

    // prologue: Q + iter-0 tiles, one commit group
#pragma unroll
    for (int l = 0; l < 4; l++) {
        int idx = t + l * 128;
        int r = idx >> 3, dq = (idx & 7) << 2;
        cpa16(&S.Qs[r][dq], &Qg[(size_t)(q0 + r) * HD_ + dq], q0 + r < N_);
    }
#pragma unroll
    for (int l = 0; l < 4; l++) {
        int idx = t + l * 128;
        int r = idx >> 3, dq = (idx & 7) << 2;
        bool mv = r < N_;   // m0 = 0
        cpa16(&S.Ks[0][r][dq], &Kg[(size_t)r * HD_ + dq], mv);
        cpa16(&S.Vs[0][r][dq], &Vg[(size_t)r * HD_ + dq], mv);
    }
#pragma unroll
    for (int l = 0; l < 8; l++) {
        int idx = t + l * 128;
        int r = idx >> 4, cq = (idx & 15) << 2;
        cpa16(&S.P2[0][r][cq], &POSg[(size_t)(q0 + r) * N_ + cq], (q0 + r < N_) && (cq < N_));
    }
    cpa_commit();

    float4 opat[4], opos[4];
#pragma unroll
    for (int i = 0; i < 4; i++) { opat[i] = make_float4(0.f,0.f,0.f,0.f); opos[i] = opat[i]; }
    float rs0 = 0.f, rs1 = 0.f;

    for (int it = 0; it < 13; it++) {
        int cur = it & 1;
        if (it < 12) {
            int nxt = (it + 1) & 1;
            int m1 = (it + 1) * 64;
#pragma unroll
            for (int l = 0; l < 4; l++) {
                int idx = t + l * 128;
                int r = idx >> 3, dq = (idx & 7) << 2;
                bool mv = m1 + r < N_;
                cpa16(&S.Ks[nxt][r][dq], &Kg[(size_t)(m1 + r) * HD_ + dq], mv);
                cpa16(&S.Vs[nxt][r][dq], &Vg[(size_t)(m1 + r) * HD_ + dq], mv);
            }
#pragma unroll
            for (int l = 0; l < 8; l++) {
                int idx = t + l * 128;
                int r = idx >> 4, cq = (idx & 15) << 2;
                cpa16(&S.P2[nxt][r][cq], &POSg[(size_t)(q0 + r) * N_ + m1 + cq],
                      (q0 + r < N_) && (m1 + cq < N_));
            }
            cpa_commit();
            asm volatile("cp.async.wait_group 1;\n" ::: "memory");
        } else {
            asm volatile("cp.async.wait_group 0;\n" ::: "memory");
        }
        __syncthreads();

        // S = Q K^T  (16 x 64 per warp)
        float4 sacc[8];
#pragma unroll
        for (int i = 0; i < 8; i++) sacc[i] = make_float4(0.f,0.f,0.f,0.f);
#pragma unroll
        for (int kk = 0; kk < 4; kk++) {
            int K0 = kk * 8;
            unsigned a0 = S.Qs[R0 + ly][K0 + lx];
            unsigned a1 = S.Qs[R0 + ly + 8][K0 + lx];
            unsigned a2 = S.Qs[R0 + ly][K0 + lx + 4];
            unsigned a3 = S.Qs[R0 + ly + 8][K0 + lx + 4];
#pragma unroll
            for (int nt = 0; nt < 8; nt++) {
                unsigned b0 = S.Ks[cur][nt * 8 + ly][K0 + lx];
                unsigned b1 = S.Ks[cur][nt * 8 + ly][K0 + lx + 4];
                mma8(sacc[nt], a0, a1, a2, a3, b0, b1);
            }
        }

        // exp + rowsum + stage P1 (warp-private rows)
        int m0 = it * 64;
#pragma unroll
        for (int nt = 0; nt < 8; nt++) {
            int mc = m0 + nt * 8 + lx * 2;
            bool mv = (mc < N_);
            float ex = mv ? __expf(sacc[nt].x) : 0.f;
            float ey = mv ? __expf(sacc[nt].y) : 0.f;
            float ez = mv ? __expf(sacc[nt].z) : 0.f;
            float ew = mv ? __expf(sacc[nt].w) : 0.f;
            rs0 += ex + ey;
            rs1 += ez + ew;
            uint2 u01; u01.x = f2tf(ex); u01.y = f2tf(ey);
            uint2 u23; u23.x = f2tf(ez); u23.y = f2tf(ew);
            *(uint2*)&S.P1[R0 + ly][nt * 8 + lx * 2] = u01;
            *(uint2*)&S.P1[R0 + ly + 8][nt * 8 + lx * 2] = u23;
        }
        __syncwarp();

        // PV: dual accumulate (16 x 32 per warp)
#pragma unroll
        for (int kk = 0; kk < 8; kk++) {
            int K0 = kk * 8;
            unsigned p0 = S.P1[R0 + ly][K0 + lx];
            unsigned p1 = S.P1[R0 + ly + 8][K0 + lx];
            unsigned p2 = S.P1[R0 + ly][K0 + lx + 4];
            unsigned p3 = S.P1[R0 + ly + 8][K0 + lx + 4];
            unsigned c0 = S.P2[cur][R0 + ly][K0 + lx];
            unsigned c1 = S.P2[cur][R0 + ly + 8][K0 + lx];
            unsigned c2 = S.P2[cur][R0 + ly][K0 + lx + 4];
            unsigned c3 = S.P2[cur][R0 + ly + 8][K0 + lx + 4];
#pragma unroll
            for (int nt = 0; nt < 4; nt++) {
                unsigned b0 = S.Vs[cur][K0 + lx][nt * 8 + ly];
                unsigned b1 = S.Vs[cur][K0 + lx + 4][nt * 8 + ly];
                mma8(opat[nt], p0, p1, p2, p3, b0, b1);
                mma8(opos[nt], c0, c1, c2, c3, b0, b1);
            }
        }
        __syncthreads();   // all reads of buf[cur] done before it is refilled
    }

    // rowsum reduce over the quad (lanes sharing a row)
    rs0 += __shfl_xor_sync(0xffffffffu, rs0, 1);
    rs0 += __shfl_xor_sync(0xffffffffu, rs0, 2);
    rs1 += __shfl_xor_sync(0xffffffffu, rs1, 1);
    rs1 += __shfl_xor_sync(0xffffffffu, rs1, 2);
    float inv0 = (1.f - gate) / rs0;
    float inv1 = (1.f - gate) / rs1;

    // epilogue: out = (1-g)/rowsum * O_patch + g * O_pos (attn sums to 1)
    int n0r = q0 + R0 + ly;
    int n1r = n0r + 8;
#pragma unroll
    for (int nt = 0; nt < 4; nt++) {
        int d = nt * 8 + lx * 2;
        if (n0r < N_) {
            float2 o;
            o.x = opat[nt].x * inv0 + gate * opos[nt].x;
            o.y = opat[nt].y * inv0 + gate * opos[nt].y;
            *(float2*)&g_att[((size_t)b * N_ + n0r) * DIM_ + h * HD_ + d] = o;
        }
        if (n1r < N_) {
            float2 o;
            o.x = opat[nt].z * inv1 + gate * opos[nt].z;
            o.y = opat[nt].w * inv1 + gate * opos[nt].w;
            *(float2*)&g_att[((size_t)b * N_ + n1r) * DIM_ + h * HD_ + d] = o;
        }
    }
}

// ---------------------------------------------------------------------------
extern "C" void kernel_launch(void* const* d_in, const int* in_sizes, int n_in,
                              void* d_out, int out_size) {
    const float* x      = (const float*)d_in[0];
    const float* Wq     = (const float*)d_in[1];
    const float* Wk     = (const float*)d_in[2];
    const float* Wv     = (const float*)d_in[3];
    const float* W_pos  = (const float*)d_in[4];
    const float* b_pos  = (const float*)d_in[5];
    const float* W_out  = (const float*)d_in[6];
    const float* b_out  = (const float*)d_in[7];
    const float* gating = (const float*)d_in[8];
    float* out = (float*)d_out;

    cudaFuncSetAttribute(attn_kernel, cudaFuncAttributeMaxDynamicSharedMemorySize,
                         (int)sizeof(ASmem));

    pos_kernel<<<H_ * N_, 256>>>(W_pos, b_pos);

    gemm_qkv<<<dim3(3 * DIM_ / 64, ROWS_ / 64), 128>>>(x, Wq, Wk, Wv);   // (18, 98)

    attn_kernel<<<dim3(13, B_ * H_), 128, sizeof(ASmem)>>>(gating);

    gemm_out<<<dim3(DIM_ / 64, ROWS_ / 64), 128>>>(W_out, b_out, out);   // (6, 98)
}